// round 16
// baseline (speedup 1.0000x reference)
#include <cuda_runtime.h>
#include <cuda_fp16.h>
#include <cstdint>

#define Bb 64
#define Nn 128
// DIN = DOUT = 64

__device__ __forceinline__ unsigned pack_f16x2(float lo_f, float hi_f) {
    unsigned r;
    asm("cvt.rn.f16x2.f32 %0, %1, %2;" : "=r"(r) : "f"(hi_f), "f"(lo_f));
    return r;
}

// fp16 m16n8k16 (fragment geometry validated rounds 8-15)
#define MMA_F16(d, a0, a1, a2, a3, b0, b1) \
    asm volatile("mma.sync.aligned.m16n8k16.row.col.f32.f16.f16.f32 " \
        "{%0,%1,%2,%3}, {%4,%5,%6,%7}, {%8,%9}, {%0,%1,%2,%3};" \
        : "+f"((d)[0]), "+f"((d)[1]), "+f"((d)[2]), "+f"((d)[3]) \
        : "r"(a0), "r"(a1), "r"(a2), "r"(a3), "r"(b0), "r"(b1))

// expand 2 adjacency bits (bit0 -> low fp16, bit1 -> high fp16) into fp16x2
__device__ __forceinline__ unsigned bits2_f16x2(unsigned w, int base) {
    unsigned t = (w >> base) & 3u;
    t = (t | (t << 15)) & 0x10001u;
    return t * 0x3C00u;
}

// ---------------------------------------------------------------------------
__device__ unsigned g_ab[Bb * Nn * 4];    // A bitmask: [b][j][q], bit p of word q = A[32q+p][j]
__device__ unsigned g_wp[64 * 32];        // W fp16x2: [e*32 + dd], dd = d/2

// ---------------------------------------------------------------------------
__global__ void build_kernel(const float* __restrict__ A,
                             const float* __restrict__ W) {
    const int b = blockIdx.x;
    const int t = threadIdx.x;
    const int w = t >> 5, lane = t & 31;

    if (t < 32) {                          // W pack for column e = b
        const int e = b;
        float w0 = W[(2 * t) * 64 + e];
        float w1 = W[(2 * t + 1) * 64 + e];
        g_wp[e * 32 + t] = pack_f16x2(w0, w1);
    }

    const float* Ab = A + (size_t)b * Nn * Nn;
    #pragma unroll 1
    for (int jj = 0; jj < 16; ++jj) {
        const int j = w * 16 + jj;
        unsigned m0 = __ballot_sync(0xFFFFFFFFu, Ab[(size_t)(lane      ) * Nn + j] != 0.0f);
        unsigned m1 = __ballot_sync(0xFFFFFFFFu, Ab[(size_t)(lane +  32) * Nn + j] != 0.0f);
        unsigned m2 = __ballot_sync(0xFFFFFFFFu, Ab[(size_t)(lane +  64) * Nn + j] != 0.0f);
        unsigned m3 = __ballot_sync(0xFFFFFFFFu, Ab[(size_t)(lane +  96) * Nn + j] != 0.0f);
        if (lane == 0)
            *(uint4*)(g_ab + ((size_t)(b * Nn + j)) * 4) = make_uint4(m0, m1, m2, m3);
    }
}

// ---------------------------------------------------------------------------
// Main: CTA per (b,i), 256 threads, 4 CTAs/SM.
//  G1: tX[k][e] = X[b,i]·W (fp16 MMA); epi: +bias, shfl -> tXB [e][kkp]
//  G2: D'[e][j] = tX^T x A (bitmask-synthesized B), warp split 1m x 8n
//      (e-tile = warp&3, j-half = warp>>2) -- halves the A-fragment LDS.
//  out staged through smem for coalesced STG.
// smem (uints, 8768 = 35,072 B):
//  phase1: sX [0,4352) swizzled fp16x2 | sW [4352,6656) | sM [6656,7168)
//  phase2: tXB [0,4352) overlay | sM live
//  phase3: outS fp32 [0,8704) overlay (covers sX/sW/sM, all dead)
//  sbias [8704,8768)
// ---------------------------------------------------------------------------
static constexpr int SMEM_BYTES = 35072;

__global__ __launch_bounds__(256, 4)
void ngnn_mma_kernel(const float* __restrict__ X,
                     const float* __restrict__ bias,
                     float* __restrict__ out) {
    extern __shared__ float sm[];
    unsigned* sX    = (unsigned*)sm;                 // swizzled [dd][k]
    unsigned* sW    = sX + 4352;                     // [e*36 + dd]
    unsigned* sM    = sX + 6656;                     // [j*4 + q] bitmask
    unsigned* tXB   = (unsigned*)sm;                 // [e*68 + kkp] overlay
    float*    outS  = (float*)sm;                    // [j*68 + e]   overlay
    float*    sbias = (float*)(sX + 8704);

    const int i = blockIdx.x;
    const int b = blockIdx.y;
    const int t = threadIdx.x;
    const int warp = t >> 5;
    const int lane = t & 31;
    const int g  = lane >> 2;
    const int tg = lane & 3;

    // ---- prologue: coalesced X LDG -> swizzled fp16x2 STS; W; mask; bias ----
    {
        const float4* xbase = (const float4*)(X + (((size_t)b * Nn + i) * Nn) * 64);
        #pragma unroll
        for (int r = 0; r < 8; ++r) {
            const int f4 = r * 256 + t;          // consecutive 16B -> coalesced
            float4 v = xbase[f4];
            const int k = f4 >> 4;               // row
            const int o = f4 & 15;               // d-chunk (4 floats)
            const int kx = k ^ (2 * ((o >> 1) & 7));
            sX[(2 * o) * 136 + kx]     = pack_f16x2(v.x, v.y);
            sX[(2 * o + 1) * 136 + kx] = pack_f16x2(v.z, v.w);
        }
        #pragma unroll
        for (int r = 0; r < 8; ++r) {
            int f = r * 256 + t;
            int e = f >> 5, dd = f & 31;
            sW[e * 36 + dd] = g_wp[f];
        }
        #pragma unroll
        for (int r = 0; r < 2; ++r) {
            int f = r * 256 + t;                 // 512 mask words, coalesced
            sM[f] = g_ab[(size_t)b * 512 + f];
        }
        if (t < 64) sbias[t] = bias[t];
    }
    __syncthreads();

    // ---- G1: single-pass fp16 MMA (validated) ----
    float acc[2][4][4];
    #pragma unroll
    for (int r = 0; r < 2; ++r)
        #pragma unroll
        for (int n = 0; n < 4; ++n)
            #pragma unroll
            for (int c = 0; c < 4; ++c) acc[r][n][c] = 0.0f;

    {
        const int q  = warp & 3;
        const int h2 = warp >> 2;
        #pragma unroll
        for (int s = 0; s < 4; ++s) {
            const int dd0 = 8 * s + tg;
            const int dd1 = dd0 + 4;
            const int x0 = 2 * ((dd0 >> 2) & 7);
            const int x1 = 2 * ((dd1 >> 2) & 7);
            unsigned ah[2][4];
            #pragma unroll
            for (int r = 0; r < 2; ++r) {
                const int kb = 32 * q + 16 * r + g;
                ah[r][0] = sX[dd0 * 136 + (kb ^ x0)];
                ah[r][1] = sX[dd0 * 136 + ((kb + 8) ^ x0)];
                ah[r][2] = sX[dd1 * 136 + (kb ^ x1)];
                ah[r][3] = sX[dd1 * 136 + ((kb + 8) ^ x1)];
            }
            #pragma unroll
            for (int nl = 0; nl < 4; ++nl) {
                const int e = 8 * (4 * h2 + nl) + g;
                const unsigned b0 = sW[e * 36 + dd0];
                const unsigned b1 = sW[e * 36 + dd1];
                #pragma unroll
                for (int r = 0; r < 2; ++r) {
                    MMA_F16(acc[r][nl], ah[r][0], ah[r][1], ah[r][2], ah[r][3], b0, b1);
                }
            }
        }
    }
    __syncthreads();   // all sX/sW reads complete before tXB overlay

    // ---- epilogue: +bias, shfl-transpose -> tXB; full-warp STS ----
    {
        const int q  = warp & 3;
        const int h2 = warp >> 2;
        const int gb = g & 1;
        #pragma unroll
        for (int r = 0; r < 2; ++r) {
            const int kkp = 16 * q + 8 * r + (g >> 1);
            #pragma unroll
            for (int nl = 0; nl < 4; ++nl) {
                const float2 bv = ((const float2*)sbias)[4 * (4 * h2 + nl) + tg];
                float c0 = acc[r][nl][0] + bv.x;
                float c1 = acc[r][nl][1] + bv.y;
                float c2 = acc[r][nl][2] + bv.x;
                float c3 = acc[r][nl][3] + bv.y;
                float u0 = __shfl_xor_sync(0xFFFFFFFFu, c0, 4);
                float u1 = __shfl_xor_sync(0xFFFFFFFFu, c1, 4);
                float u2 = __shfl_xor_sync(0xFFFFFFFFu, c2, 4);
                float u3 = __shfl_xor_sync(0xFFFFFFFFu, c3, 4);
                const int e0 = 8 * (4 * h2 + nl) + 2 * tg + gb;
                unsigned w0 = gb ? pack_f16x2(u1, c1) : pack_f16x2(c0, u0);
                unsigned w1 = gb ? pack_f16x2(u3, c3) : pack_f16x2(c2, u2);
                tXB[e0 * 68 + kkp]     = w0;
                tXB[e0 * 68 + kkp + 4] = w1;
            }
        }
    }
    __syncthreads();

    // ---- G2: fp16 MMA, D'[e][j], 1 e-tile x 8 j-tiles per warp ----
    float acc2[8][4];
    #pragma unroll
    for (int n = 0; n < 8; ++n)
        #pragma unroll
        for (int c = 0; c < 4; ++c) acc2[n][c] = 0.0f;

    const int et = warp & 3;               // e m-tile (rows 16et..16et+15)
    const int jh = warp >> 2;               // j half (tiles 8jh..8jh+7)
    {
        // mask words for this warp's 8 j-rows (broadcast LDS.128, CF)
        uint4 mw[8];
        #pragma unroll
        for (int nl = 0; nl < 8; ++nl) {
            const int jc = 8 * (8 * jh + nl) + g;
            mw[nl] = *(const uint4*)(sM + 4 * jc);
        }
        const int eb = 16 * et + g;
        #pragma unroll
        for (int s = 0; s < 8; ++s) {
            const int kk0 = 8 * s + tg;
            const int kk1 = kk0 + 4;
            const int base = (s & 1) * 16 + 2 * tg;
            unsigned a0 = tXB[eb * 68 + kk0];
            unsigned a1 = tXB[(eb + 8) * 68 + kk0];
            unsigned a2 = tXB[eb * 68 + kk1];
            unsigned a3 = tXB[(eb + 8) * 68 + kk1];
            #pragma unroll
            for (int nl = 0; nl < 8; ++nl) {
                const unsigned w = (s < 2) ? mw[nl].x : (s < 4) ? mw[nl].y
                                 : (s < 6) ? mw[nl].z : mw[nl].w;
                const unsigned b0 = bits2_f16x2(w, base);
                const unsigned b1 = bits2_f16x2(w, base + 8);
                MMA_F16(acc2[nl], a0, a1, a2, a3, b0, b1);
            }
        }
    }
    __syncthreads();   // tXB + sM reads done before outS overwrite

    // ---- stage D'[e][j] -> outS [j*68 + e] (CF banks) ----
    {
        const int e0 = 16 * et + g;
        #pragma unroll
        for (int nl = 0; nl < 8; ++nl) {
            const int j0 = 8 * (8 * jh + nl) + 2 * tg;
            outS[j0 * 68 + e0]           = acc2[nl][0];
            outS[(j0 + 1) * 68 + e0]     = acc2[nl][1];
            outS[j0 * 68 + e0 + 8]       = acc2[nl][2];
            outS[(j0 + 1) * 68 + e0 + 8] = acc2[nl][3];
        }
    }
    __syncthreads();

    // ---- coalesced copy outS -> out[b,i,:,:] ----
    {
        float4* outp = (float4*)(out + (((size_t)b * Nn + i) * Nn) * 64);
        #pragma unroll
        for (int r = 0; r < 8; ++r) {
            const int f4 = r * 256 + t;
            const int j = f4 >> 4, c4 = f4 & 15;
            outp[f4] = *(const float4*)(outS + j * 68 + 4 * c4);
        }
    }
}

// ---------------------------------------------------------------------------
extern "C" void kernel_launch(void* const* d_in, const int* in_sizes, int n_in,
                              void* d_out, int out_size) {
    const float* X    = (const float*)d_in[0];  // [B,N,N,DIN]
    const float* A    = (const float*)d_in[1];  // [B,N,N]
    const float* W    = (const float*)d_in[2];  // [DIN,DOUT]
    const float* bias = (const float*)d_in[3];  // [DOUT]
    float* out = (float*)d_out;                 // [B,N,N,DOUT]

    build_kernel<<<Bb, 256>>>(A, W);

    cudaFuncSetAttribute(ngnn_mma_kernel,
                         cudaFuncAttributeMaxDynamicSharedMemorySize, SMEM_BYTES);
    dim3 grid(Nn, Bb);
    ngnn_mma_kernel<<<grid, 256, SMEM_BYTES>>>(X, bias, out);
}

// round 17
// speedup vs baseline: 1.3005x; 1.3005x over previous
#include <cuda_runtime.h>
#include <cuda_fp16.h>
#include <cstdint>

#define Bb 64
#define Nn 128
// DIN = DOUT = 64

__device__ __forceinline__ unsigned pack_f16x2(float lo_f, float hi_f) {
    unsigned r;
    asm("cvt.rn.f16x2.f32 %0, %1, %2;" : "=r"(r) : "f"(hi_f), "f"(lo_f));
    return r;
}

// fp16 m16n8k16 (fragment geometry validated rounds 8-16)
#define MMA_F16(d, a0, a1, a2, a3, b0, b1) \
    asm volatile("mma.sync.aligned.m16n8k16.row.col.f32.f16.f16.f32 " \
        "{%0,%1,%2,%3}, {%4,%5,%6,%7}, {%8,%9}, {%0,%1,%2,%3};" \
        : "+f"((d)[0]), "+f"((d)[1]), "+f"((d)[2]), "+f"((d)[3]) \
        : "r"(a0), "r"(a1), "r"(a2), "r"(a3), "r"(b0), "r"(b1))

// expand 2 adjacency bits (bit0 -> low fp16, bit1 -> high fp16) into fp16x2
__device__ __forceinline__ unsigned bits2_f16x2(unsigned w, int base) {
    unsigned t = (w >> base) & 3u;
    t = (t | (t << 15)) & 0x10001u;
    return t * 0x3C00u;
}

// ---------------------------------------------------------------------------
__device__ unsigned g_ab[Bb * Nn * 4];    // A bitmask: [b][j][q], bit p of word q = A[32q+p][j]
__device__ unsigned g_wp[64 * 32];        // W fp16x2: [e*32 + dd], dd = d/2

// ---------------------------------------------------------------------------
__global__ void build_kernel(const float* __restrict__ A,
                             const float* __restrict__ W) {
    const int b = blockIdx.x;
    const int t = threadIdx.x;
    const int w = t >> 5, lane = t & 31;

    if (t < 32) {                          // W pack for column e = b
        const int e = b;
        float w0 = W[(2 * t) * 64 + e];
        float w1 = W[(2 * t + 1) * 64 + e];
        g_wp[e * 32 + t] = pack_f16x2(w0, w1);
    }

    const float* Ab = A + (size_t)b * Nn * Nn;
    #pragma unroll 1
    for (int jj = 0; jj < 16; ++jj) {
        const int j = w * 16 + jj;
        unsigned m0 = __ballot_sync(0xFFFFFFFFu, Ab[(size_t)(lane      ) * Nn + j] != 0.0f);
        unsigned m1 = __ballot_sync(0xFFFFFFFFu, Ab[(size_t)(lane +  32) * Nn + j] != 0.0f);
        unsigned m2 = __ballot_sync(0xFFFFFFFFu, Ab[(size_t)(lane +  64) * Nn + j] != 0.0f);
        unsigned m3 = __ballot_sync(0xFFFFFFFFu, Ab[(size_t)(lane +  96) * Nn + j] != 0.0f);
        if (lane == 0)
            *(uint4*)(g_ab + ((size_t)(b * Nn + j)) * 4) = make_uint4(m0, m1, m2, m3);
    }
}

// ---------------------------------------------------------------------------
// Main: CTA per (b,i), 256 threads, 4 CTAs/SM.
//  G1: tX[k][e] = X[b,i]·W (fp16 MMA); epi: +bias, shfl -> tXB [e][kkp]
//  G2 (SWAPPED): D[j][e] = A^T(j,k) x tX(k,e).
//      A operand = adjacency synthesized from bitmask (64 synth/warp),
//      B operand = tX from tXB (64 LDS.32/warp) -- round-15 economics,
//      but accumulators land in out[j][e] orientation -> DIRECT STG.64,
//      no smem staging, two fewer barriers.
// smem (uints, 8768 = 35,072 B):
//  phase1: sX [0,4352) swizzled fp16x2 | sW [4352,6656) | sM [6656,7168)
//  phase2: tXB [0,4352) overlay | sM live
//  sbias [8704,8768)
// ---------------------------------------------------------------------------
static constexpr int SMEM_BYTES = 35072;

__global__ __launch_bounds__(256, 4)
void ngnn_mma_kernel(const float* __restrict__ X,
                     const float* __restrict__ bias,
                     float* __restrict__ out) {
    extern __shared__ float sm[];
    unsigned* sX    = (unsigned*)sm;                 // swizzled [dd][k]
    unsigned* sW    = sX + 4352;                     // [e*36 + dd]
    unsigned* sM    = sX + 6656;                     // [j*4 + q] bitmask
    unsigned* tXB   = (unsigned*)sm;                 // [e*68 + kkp] overlay
    float*    sbias = (float*)(sX + 8704);

    const int i = blockIdx.x;
    const int b = blockIdx.y;
    const int t = threadIdx.x;
    const int warp = t >> 5;
    const int lane = t & 31;
    const int g  = lane >> 2;
    const int tg = lane & 3;

    // ---- prologue: coalesced X LDG -> swizzled fp16x2 STS; W; mask; bias ----
    {
        const float4* xbase = (const float4*)(X + (((size_t)b * Nn + i) * Nn) * 64);
        #pragma unroll
        for (int r = 0; r < 8; ++r) {
            const int f4 = r * 256 + t;          // consecutive 16B -> coalesced
            float4 v = xbase[f4];
            const int k = f4 >> 4;               // row
            const int o = f4 & 15;               // d-chunk (4 floats)
            const int kx = k ^ (2 * ((o >> 1) & 7));
            sX[(2 * o) * 136 + kx]     = pack_f16x2(v.x, v.y);
            sX[(2 * o + 1) * 136 + kx] = pack_f16x2(v.z, v.w);
        }
        #pragma unroll
        for (int r = 0; r < 8; ++r) {
            int f = r * 256 + t;
            int e = f >> 5, dd = f & 31;
            sW[e * 36 + dd] = g_wp[f];
        }
        #pragma unroll
        for (int r = 0; r < 2; ++r) {
            int f = r * 256 + t;                 // 512 mask words, coalesced
            sM[f] = g_ab[(size_t)b * 512 + f];
        }
        if (t < 64) sbias[t] = bias[t];
    }
    __syncthreads();

    // ---- G1: single-pass fp16 MMA (validated) ----
    float acc[2][4][4];
    #pragma unroll
    for (int r = 0; r < 2; ++r)
        #pragma unroll
        for (int n = 0; n < 4; ++n)
            #pragma unroll
            for (int c = 0; c < 4; ++c) acc[r][n][c] = 0.0f;

    {
        const int q  = warp & 3;
        const int h2 = warp >> 2;
        #pragma unroll
        for (int s = 0; s < 4; ++s) {
            const int dd0 = 8 * s + tg;
            const int dd1 = dd0 + 4;
            const int x0 = 2 * ((dd0 >> 2) & 7);
            const int x1 = 2 * ((dd1 >> 2) & 7);
            unsigned ah[2][4];
            #pragma unroll
            for (int r = 0; r < 2; ++r) {
                const int kb = 32 * q + 16 * r + g;
                ah[r][0] = sX[dd0 * 136 + (kb ^ x0)];
                ah[r][1] = sX[dd0 * 136 + ((kb + 8) ^ x0)];
                ah[r][2] = sX[dd1 * 136 + (kb ^ x1)];
                ah[r][3] = sX[dd1 * 136 + ((kb + 8) ^ x1)];
            }
            #pragma unroll
            for (int nl = 0; nl < 4; ++nl) {
                const int e = 8 * (4 * h2 + nl) + g;
                const unsigned b0 = sW[e * 36 + dd0];
                const unsigned b1 = sW[e * 36 + dd1];
                #pragma unroll
                for (int r = 0; r < 2; ++r) {
                    MMA_F16(acc[r][nl], ah[r][0], ah[r][1], ah[r][2], ah[r][3], b0, b1);
                }
            }
        }
    }
    __syncthreads();   // all sX/sW reads complete before tXB overlay

    // ---- epilogue: +bias, shfl-transpose -> tXB; full-warp STS ----
    {
        const int q  = warp & 3;
        const int h2 = warp >> 2;
        const int gb = g & 1;
        #pragma unroll
        for (int r = 0; r < 2; ++r) {
            const int kkp = 16 * q + 8 * r + (g >> 1);
            #pragma unroll
            for (int nl = 0; nl < 4; ++nl) {
                const float2 bv = ((const float2*)sbias)[4 * (4 * h2 + nl) + tg];
                float c0 = acc[r][nl][0] + bv.x;
                float c1 = acc[r][nl][1] + bv.y;
                float c2 = acc[r][nl][2] + bv.x;
                float c3 = acc[r][nl][3] + bv.y;
                float u0 = __shfl_xor_sync(0xFFFFFFFFu, c0, 4);
                float u1 = __shfl_xor_sync(0xFFFFFFFFu, c1, 4);
                float u2 = __shfl_xor_sync(0xFFFFFFFFu, c2, 4);
                float u3 = __shfl_xor_sync(0xFFFFFFFFu, c3, 4);
                const int e0 = 8 * (4 * h2 + nl) + 2 * tg + gb;
                unsigned w0 = gb ? pack_f16x2(u1, c1) : pack_f16x2(c0, u0);
                unsigned w1 = gb ? pack_f16x2(u3, c3) : pack_f16x2(c2, u2);
                tXB[e0 * 68 + kkp]     = w0;
                tXB[e0 * 68 + kkp + 4] = w1;
            }
        }
    }
    __syncthreads();

    // ---- G2 (swapped): D[j][e] = A^T x tX; A synth from bitmask ----
    float acc2[2][4][4];
    #pragma unroll
    for (int r = 0; r < 2; ++r)
        #pragma unroll
        for (int n = 0; n < 4; ++n)
            #pragma unroll
            for (int c = 0; c < 4; ++c) acc2[r][n][c] = 0.0f;

    const int q  = warp & 3;               // j-tile pair: rows 32q..32q+31
    const int h2 = warp >> 2;              // e-half: cols 32h2..32h2+31
    {
        // mask words for this thread's 4 j-rows (1-wf LDS.128 each)
        uint4 mw[2][2];
        #pragma unroll
        for (int r = 0; r < 2; ++r) {
            const int j0 = 32 * q + 16 * r + g;
            mw[r][0] = *(const uint4*)(sM + 4 * j0);
            mw[r][1] = *(const uint4*)(sM + 4 * (j0 + 8));
        }
        #pragma unroll
        for (int s = 0; s < 8; ++s) {
            const int kkp  = 8 * s + tg;
            const int base = 16 * (s & 1) + 2 * tg;
            // A-frags: adjacency rows j (synth), k-pairs along K
            unsigned a[2][4];
            #pragma unroll
            for (int r = 0; r < 2; ++r) {
                const unsigned wj0 = (s < 2) ? mw[r][0].x : (s < 4) ? mw[r][0].y
                                  : (s < 6) ? mw[r][0].z : mw[r][0].w;
                const unsigned wj1 = (s < 2) ? mw[r][1].x : (s < 4) ? mw[r][1].y
                                  : (s < 6) ? mw[r][1].z : mw[r][1].w;
                a[r][0] = bits2_f16x2(wj0, base);
                a[r][1] = bits2_f16x2(wj1, base);
                a[r][2] = bits2_f16x2(wj0, base + 8);
                a[r][3] = bits2_f16x2(wj1, base + 8);
            }
            // B-frags: tX columns e (LDS from tXB)
            #pragma unroll
            for (int nl = 0; nl < 4; ++nl) {
                const int e = 8 * (4 * h2 + nl) + g;
                const unsigned b0 = tXB[e * 68 + kkp];
                const unsigned b1 = tXB[e * 68 + kkp + 4];
                #pragma unroll
                for (int r = 0; r < 2; ++r) {
                    MMA_F16(acc2[r][nl], a[r][0], a[r][1], a[r][2], a[r][3], b0, b1);
                }
            }
        }
    }

    // ---- direct write: D[j][e] -> out[b,i,j,e] (STG.64, no staging) ----
    {
        float* outp = out + (((size_t)b * Nn + i) * Nn) * 64;
        #pragma unroll
        for (int r = 0; r < 2; ++r) {
            const int j0 = 32 * q + 16 * r + g;
            #pragma unroll
            for (int nl = 0; nl < 4; ++nl) {
                const int e0 = 8 * (4 * h2 + nl) + 2 * tg;
                *(float2*)(outp + (size_t)j0 * 64 + e0) =
                    make_float2(acc2[r][nl][0], acc2[r][nl][1]);
                *(float2*)(outp + (size_t)(j0 + 8) * 64 + e0) =
                    make_float2(acc2[r][nl][2], acc2[r][nl][3]);
            }
        }
    }
}

// ---------------------------------------------------------------------------
extern "C" void kernel_launch(void* const* d_in, const int* in_sizes, int n_in,
                              void* d_out, int out_size) {
    const float* X    = (const float*)d_in[0];  // [B,N,N,DIN]
    const float* A    = (const float*)d_in[1];  // [B,N,N]
    const float* W    = (const float*)d_in[2];  // [DIN,DOUT]
    const float* bias = (const float*)d_in[3];  // [DOUT]
    float* out = (float*)d_out;                 // [B,N,N,DOUT]

    build_kernel<<<Bb, 256>>>(A, W);

    cudaFuncSetAttribute(ngnn_mma_kernel,
                         cudaFuncAttributeMaxDynamicSharedMemorySize, SMEM_BYTES);
    dim3 grid(Nn, Bb);
    ngnn_mma_kernel<<<grid, 256, SMEM_BYTES>>>(X, bias, out);
}